// round 5
// baseline (speedup 1.0000x reference)
#include <cuda_runtime.h>

#define BATCH 16
#define CH    256
#define IH    100
#define IW    100
#define NBOX  100
#define RH    40
#define RW    40
#define NCLS  599
#define CPB   2          // channels per CTA in resize/pool kernel (known-good)
#define CCHUNK 15        // classes per CTA in class_mean kernel
#define NCHUNK 40        // ceil(599/15)

// Scratch (no allocations allowed)
__device__ float g_pooled[BATCH * NBOX * CH];   // [B][N][C]  (coalesced reads in k2)
__device__ int   g_counts[BATCH * NCLS];        // valid boxes per (b, cls)
__device__ int   g_precls[BATCH * NBOX];        // valid ? cls : -1

// Quantize one box (xyxy, image coords) to the 40x40 grid. Matches
// jnp.round (half-to-even) + clip semantics of the reference.
__device__ __forceinline__ int quantize_box(float4 bb, bool& valid) {
    const float s = 40.0f / 1024.0f;            // exact in fp32
    int x1 = max((int)rintf(bb.x * s), 0);
    int y1 = max((int)rintf(bb.y * s), 0);
    int x2 = min((int)rintf(bb.z * s), RW);
    int y2 = min((int)rintf(bb.w * s), RH);
    valid = (x1 < x2) && (y1 < y2);
    x1 = min(max(x1, 0), RW);  x2 = min(max(x2, 0), RW);
    y1 = min(max(y1, 0), RH);  y2 = min(max(y2, 0), RH);
    return x1 | (y1 << 8) | (x2 << 16) | (y2 << 24);
}

// ---------------------------------------------------------------------------
// Kernel 1: per (b, 2 channels) — bilinear 100->40 resize into smem, then
// direct box-sum pooling (boxes are <=5x5 cells on the 40x40 grid).
// The cbas==0 CTA of each batch also produces g_counts / g_precls.
// ---------------------------------------------------------------------------
__global__ __launch_bounds__(256) void resize_pool_kernel(
        const float* __restrict__ feat, const float* __restrict__ boxes,
        const int* __restrict__ gt) {
    __shared__ float res[CPB][RH * RW];         // 12.8 KB
    __shared__ int   s_box[NBOX];               // packed x1,y1,x2,y2 (0 if invalid)
    __shared__ float s_pool[NBOX][CPB];         // staged for float2 writes

    const int blk  = blockIdx.x;                // 0 .. BATCH*CH/CPB-1
    const int b    = blk / (CH / CPB);
    const int cbas = (blk % (CH / CPB)) * CPB;
    const int tid  = threadIdx.x;
    const bool meta_cta = (cbas == 0);

    // --- quantize this batch's boxes (threads 0..99) ---
    bool v_me = false;
    if (tid < NBOX) {
        float4 bb = __ldg((const float4*)boxes + b * NBOX + tid);
        int pk = quantize_box(bb, v_me);
        s_box[tid] = v_me ? pk : 0;             // invalid -> x1==x2==0
    }
    // --- meta CTA: zero this batch's class counts (before the barrier) ---
    if (meta_cta) {
        for (int i = tid; i < NCLS; i += 256) g_counts[b * NCLS + i] = 0;
    }

    // --- bilinear resize (half-pixel centers): src = 2.5*dst + 0.75 ---
    const float* __restrict__ in0 = feat + (size_t)(b * CH + cbas) * (IH * IW);
    const float* __restrict__ in1 = in0 + IH * IW;
    for (int i = tid; i < RH * RW; i += 256) {
        int oy = i / RW, ox = i % RW;
        float sy = 2.5f * (float)oy + 0.75f;    // frac is exactly .75 or .25
        float sx = 2.5f * (float)ox + 0.75f;
        int y0 = (int)sy;  float fy = sy - (float)y0;
        int x0 = (int)sx;  float fx = sx - (float)x0;
        int off = y0 * IW + x0;
        float gx0 = 1.0f - fx, gy0 = 1.0f - fy;
        float a00 = __ldg(in0 + off),      a01 = __ldg(in0 + off + 1);
        float a10 = __ldg(in0 + off + IW), a11 = __ldg(in0 + off + IW + 1);
        float b00 = __ldg(in1 + off),      b01 = __ldg(in1 + off + 1);
        float b10 = __ldg(in1 + off + IW), b11 = __ldg(in1 + off + IW + 1);
        res[0][i] = gy0 * (gx0 * a00 + fx * a01) + fy * (gx0 * a10 + fx * a11);
        res[1][i] = gy0 * (gx0 * b00 + fx * b01) + fy * (gx0 * b10 + fx * b11);
    }
    __syncthreads();

    // --- meta CTA: per-class counts + per-box class tags (post-barrier) ---
    if (meta_cta && tid < NBOX) {
        int cls = __ldg(gt + b * NBOX + tid);
        g_precls[b * NBOX + tid] = v_me ? cls : -1;
        if (v_me) atomicAdd(&g_counts[b * NCLS + cls], 1);
    }

    // --- direct box-average pooling: thread = (plane, box) ---
    if (tid < NBOX * CPB) {
        int n = tid % NBOX;
        int p = tid / NBOX;
        int pk = s_box[n];
        int x1 = pk & 0xFF, y1 = (pk >> 8) & 0xFF;
        int x2 = (pk >> 16) & 0xFF, y2 = (pk >> 24) & 0xFF;
        float out = 0.0f;
        if (x1 < x2) {                          // valid (invalid stored as 0)
            float s = 0.0f;
            const float* r = res[p];
            for (int y = y1; y < y2; y++) {
                float rs = 0.0f;
                for (int x = x1; x < x2; x++) rs += r[y * RW + x];
                s += rs;
            }
            out = s / (float)((y2 - y1) * (x2 - x1));
        }
        s_pool[n][p] = out;
    }
    __syncthreads();

    // --- transposed write: one float2 per box into [B][N][C] ---
    if (tid < NBOX) {
        float2 v2 = make_float2(s_pool[tid][0], s_pool[tid][1]);
        *(float2*)(g_pooled + (size_t)(b * NBOX + tid) * CH + cbas) = v2;
    }
}

// ---------------------------------------------------------------------------
// Kernel 2: scatter-mean. One CTA per (class-chunk, batch); thread = channel.
// Batch metadata (precls + chunk counts) loaded into smem ONCE, then 15
// classes processed per CTA. Empty classes (~96% of chunk entries overall)
// cost one coalesced 1KB zero write. Non-empty classes sum in ascending box
// order (deterministic, matching segment_sum accumulation order).
// ---------------------------------------------------------------------------
__global__ __launch_bounds__(CH) void class_mean_kernel(float* __restrict__ out) {
    __shared__ int s_cls[NBOX];
    __shared__ int s_cnt[CCHUNK];

    const int c0  = blockIdx.x * CCHUNK;   // first class of this chunk
    const int b   = blockIdx.y;            // 0..15
    const int tid = threadIdx.x;           // channel

    if (tid < NBOX)
        s_cls[tid] = __ldg(&g_precls[b * NBOX + tid]);
    if (tid < CCHUNK) {
        int c = c0 + tid;
        s_cnt[tid] = (c < NCLS) ? __ldg(&g_counts[b * NCLS + c]) : 0;
    }
    __syncthreads();

    const float* __restrict__ pool = g_pooled + (size_t)b * NBOX * CH + tid;

    #pragma unroll
    for (int j = 0; j < CCHUNK; j++) {
        int cls = c0 + j;
        if (cls >= NCLS) break;
        int cnt = s_cnt[j];                // uniform across CTA
        float r = 0.0f;
        if (cnt > 0) {
            float sum = 0.0f;
            for (int n = 0; n < NBOX; n++)
                if (s_cls[n] == cls)       // uniform predicate
                    sum += __ldg(pool + (size_t)n * CH);
            r = sum / (float)cnt;
        }
        out[(size_t)(b * NCLS + cls) * CH + tid] = r;
    }
}

// ---------------------------------------------------------------------------
extern "C" void kernel_launch(void* const* d_in, const int* in_sizes, int n_in,
                              void* d_out, int out_size) {
    const float* feat  = (const float*)d_in[0];   // [16,256,100,100] f32
    const float* boxes = (const float*)d_in[1];   // [16,100,4] f32
    const int*   gt    = (const int*)d_in[2];     // [16,100] i32
    float* out = (float*)d_out;                   // [16,599,256] f32

    resize_pool_kernel<<<BATCH * (CH / CPB), 256>>>(feat, boxes, gt);
    dim3 g2(NCHUNK, BATCH);
    class_mean_kernel<<<g2, CH>>>(out);
}

// round 6
// speedup vs baseline: 1.4068x; 1.4068x over previous
#include <cuda_runtime.h>

#define BATCH 16
#define CH    256
#define IH    100
#define IW    100
#define NBOX  100
#define RH    40
#define RW    40
#define NCLS  599
#define CPB   2          // channels per CTA in resize/pool kernel (known-good)

// Scratch (no allocations allowed)
__device__ float g_pooled[BATCH * NBOX * CH];   // [B][N][C]  (coalesced reads in k2)
__device__ int   g_precls[BATCH * NBOX];        // valid ? cls : -1

// Quantize one box (xyxy, image coords) to the 40x40 grid. Matches
// jnp.round (half-to-even) + clip semantics of the reference.
__device__ __forceinline__ int quantize_box(float4 bb, bool& valid) {
    const float s = 40.0f / 1024.0f;            // exact in fp32
    int x1 = max((int)rintf(bb.x * s), 0);
    int y1 = max((int)rintf(bb.y * s), 0);
    int x2 = min((int)rintf(bb.z * s), RW);
    int y2 = min((int)rintf(bb.w * s), RH);
    valid = (x1 < x2) && (y1 < y2);
    x1 = min(max(x1, 0), RW);  x2 = min(max(x2, 0), RW);
    y1 = min(max(y1, 0), RH);  y2 = min(max(y2, 0), RH);
    return x1 | (y1 << 8) | (x2 << 16) | (y2 << 24);
}

// ---------------------------------------------------------------------------
// Kernel 1: per (b, 2 channels) — bilinear 100->40 resize into smem, then
// direct box-sum pooling (boxes are <=5x5 cells on the 40x40 grid).
// The cbas==0 CTA of each batch also produces g_precls.
// ---------------------------------------------------------------------------
__global__ __launch_bounds__(256) void resize_pool_kernel(
        const float* __restrict__ feat, const float* __restrict__ boxes,
        const int* __restrict__ gt) {
    __shared__ float res[CPB][RH * RW];         // 12.8 KB
    __shared__ int   s_box[NBOX];               // packed x1,y1,x2,y2 (0 if invalid)
    __shared__ float s_pool[NBOX][CPB];         // staged for float2 writes

    const int blk  = blockIdx.x;                // 0 .. BATCH*CH/CPB-1
    const int b    = blk / (CH / CPB);
    const int cbas = (blk % (CH / CPB)) * CPB;
    const int tid  = threadIdx.x;

    // --- quantize this batch's boxes (threads 0..99) ---
    bool v_me = false;
    if (tid < NBOX) {
        float4 bb = __ldg((const float4*)boxes + b * NBOX + tid);
        int pk = quantize_box(bb, v_me);
        s_box[tid] = v_me ? pk : 0;             // invalid -> x1==x2==0
        // meta CTA: per-box class tag (no barrier needed; k2 consumes later)
        if (cbas == 0) {
            int cls = __ldg(gt + b * NBOX + tid);
            g_precls[b * NBOX + tid] = v_me ? cls : -1;
        }
    }

    // --- bilinear resize (half-pixel centers): src = 2.5*dst + 0.75 ---
    const float* __restrict__ in0 = feat + (size_t)(b * CH + cbas) * (IH * IW);
    const float* __restrict__ in1 = in0 + IH * IW;
    for (int i = tid; i < RH * RW; i += 256) {
        int oy = i / RW, ox = i % RW;
        float sy = 2.5f * (float)oy + 0.75f;    // frac is exactly .75 or .25
        float sx = 2.5f * (float)ox + 0.75f;
        int y0 = (int)sy;  float fy = sy - (float)y0;
        int x0 = (int)sx;  float fx = sx - (float)x0;
        int off = y0 * IW + x0;
        float gx0 = 1.0f - fx, gy0 = 1.0f - fy;
        float a00 = __ldg(in0 + off),      a01 = __ldg(in0 + off + 1);
        float a10 = __ldg(in0 + off + IW), a11 = __ldg(in0 + off + IW + 1);
        float b00 = __ldg(in1 + off),      b01 = __ldg(in1 + off + 1);
        float b10 = __ldg(in1 + off + IW), b11 = __ldg(in1 + off + IW + 1);
        res[0][i] = gy0 * (gx0 * a00 + fx * a01) + fy * (gx0 * a10 + fx * a11);
        res[1][i] = gy0 * (gx0 * b00 + fx * b01) + fy * (gx0 * b10 + fx * b11);
    }
    __syncthreads();

    // --- direct box-average pooling: thread = (plane, box) ---
    if (tid < NBOX * CPB) {
        int n = tid % NBOX;
        int p = tid / NBOX;
        int pk = s_box[n];
        int x1 = pk & 0xFF, y1 = (pk >> 8) & 0xFF;
        int x2 = (pk >> 16) & 0xFF, y2 = (pk >> 24) & 0xFF;
        float out = 0.0f;
        if (x1 < x2) {                          // valid (invalid stored as 0)
            float s = 0.0f;
            const float* r = res[p];
            for (int y = y1; y < y2; y++) {
                float rs = 0.0f;
                for (int x = x1; x < x2; x++) rs += r[y * RW + x];
                s += rs;
            }
            out = s / (float)((y2 - y1) * (x2 - x1));
        }
        s_pool[n][p] = out;
    }
    __syncthreads();

    // --- transposed write: one float2 per box into [B][N][C] ---
    if (tid < NBOX) {
        float2 v2 = make_float2(s_pool[tid][0], s_pool[tid][1]);
        *(float2*)(g_pooled + (size_t)(b * NBOX + tid) * CH + cbas) = v2;
    }
}

// ---------------------------------------------------------------------------
// Kernel 2: scatter-mean per (b, class). One CTA per (class, b); 128 threads,
// 2 channels each (float2). Single dependent load (g_precls, 400B coalesced),
// cnt via __syncthreads_count; empty classes = load + zero store, done.
// Non-empty: ballot-compacted ascending box list (segment_sum order).
// ---------------------------------------------------------------------------
__global__ __launch_bounds__(128) void class_mean_kernel(float* __restrict__ out) {
    __shared__ int s_list[NBOX];
    __shared__ int s_wcnt[4];

    const int cls = blockIdx.x;   // 0..598
    const int b   = blockIdx.y;   // 0..15
    const int tid = threadIdx.x;  // channel pair: handles 2*tid, 2*tid+1
    float2* __restrict__ o =
        (float2*)(out + (size_t)(b * NCLS + cls) * CH) + tid;

    bool m = (tid < NBOX) && (__ldg(&g_precls[b * NBOX + tid]) == cls);
    const int wid  = tid >> 5;
    const int lane = tid & 31;
    unsigned bal = __ballot_sync(0xffffffffu, m);
    if (lane == 0) s_wcnt[wid] = __popc(bal);
    int cnt = __syncthreads_count(m);

    if (cnt == 0) { *o = make_float2(0.0f, 0.0f); return; }

    if (m) {
        int base = 0;
        #pragma unroll
        for (int w = 0; w < 4; w++) base += (w < wid) ? s_wcnt[w] : 0;
        s_list[base + __popc(bal & ((1u << lane) - 1u))] = tid;   // ascending n
    }
    __syncthreads();

    float sx = 0.0f, sy = 0.0f;
    const float2* __restrict__ pool =
        (const float2*)(g_pooled + (size_t)b * NBOX * CH) + tid;
    for (int j = 0; j < cnt; j++) {
        float2 v = __ldg(pool + (size_t)s_list[j] * (CH / 2));
        sx += v.x;  sy += v.y;
    }
    float inv = 1.0f / (float)cnt;
    *o = make_float2(sx * inv, sy * inv);
}

// ---------------------------------------------------------------------------
extern "C" void kernel_launch(void* const* d_in, const int* in_sizes, int n_in,
                              void* d_out, int out_size) {
    const float* feat  = (const float*)d_in[0];   // [16,256,100,100] f32
    const float* boxes = (const float*)d_in[1];   // [16,100,4] f32
    const int*   gt    = (const int*)d_in[2];     // [16,100] i32
    float* out = (float*)d_out;                   // [16,599,256] f32

    resize_pool_kernel<<<BATCH * (CH / CPB), 256>>>(feat, boxes, gt);
    dim3 g2(NCLS, BATCH);
    class_mean_kernel<<<g2, 128>>>(out);
}